// round 16
// baseline (speedup 1.0000x reference)
#include <cuda_runtime.h>
#include <cuda_fp16.h>
#include <math.h>
#include <stdint.h>

// Problem constants
#define BB 16
#define NN 1024
#define FF 256
#define ALPHA 0.2f

// Scratch (device globals — no allocations allowed)
__device__ __half g_h16[(size_t)BB * NN * FF];      // 8 MB  h in fp16
__device__ __half g_Wt16[FF * FF];                  // W^T fp16 [o][f]
__device__ __half g_WhT[(size_t)BB * FF * NN];      // 8 MB  [b][o][j] fp16
__device__ float g_u[2 * FF];                       // u1 = W@a1, u2 = W@a2
__device__ float g_f1[BB * NN];
__device__ float g_f2[BB * NN];
__device__ float g_maxf2[BB];
__device__ __half g_P[(size_t)BB * NN * NN];        // 32 MB shifted exp, fp16
__device__ float g_invden[BB * NN];                 // 1 / row sum (of shifted exps)

// ---------------------------------------------------------------------------
// Helpers
// ---------------------------------------------------------------------------
__device__ __forceinline__ void cp16(uint32_t saddr, const void* gptr) {
    asm volatile("cp.async.cg.shared.global [%0], [%1], 16;"
                 :: "r"(saddr), "l"(gptr) : "memory");
}

__device__ __forceinline__ uint32_t smem_u32(const void* p) {
    uint32_t a;
    asm("{ .reg .u64 t; cvta.to.shared.u64 t, %1; cvt.u32.u64 %0, t; }"
        : "=r"(a) : "l"(p));
    return a;
}

__device__ __forceinline__ void mma_f16(float* c, const uint32_t* a, const uint32_t* b) {
    asm volatile(
        "mma.sync.aligned.m16n8k16.row.col.f32.f16.f16.f32 "
        "{%0,%1,%2,%3}, {%4,%5,%6,%7}, {%8,%9}, {%0,%1,%2,%3};"
        : "+f"(c[0]), "+f"(c[1]), "+f"(c[2]), "+f"(c[3])
        : "r"(a[0]), "r"(a[1]), "r"(a[2]), "r"(a[3]), "r"(b[0]), "r"(b[1]));
}

__device__ __forceinline__ void ldm_x4(uint32_t& d0, uint32_t& d1,
                                       uint32_t& d2, uint32_t& d3, uint32_t a) {
    asm volatile("ldmatrix.sync.aligned.m8n8.x4.shared.b16 {%0,%1,%2,%3}, [%4];"
                 : "=r"(d0), "=r"(d1), "=r"(d2), "=r"(d3) : "r"(a));
}

// Shared tile geometry (both fp16 GEMMs)
#define BM 128
#define BN 128
#define BK2 64
#define PADU 36                       // u32 row pitch (32 data + 4 pad)
#define A2_TILE_U (128 * PADU)
#define B2_TILE_U (128 * PADU)
#define STAGE2_U (A2_TILE_U + B2_TILE_U)    // 9216 u32 = 36864 B
#define G2_SMEM (3 * STAGE2_U * 4)          // 110592 B
#define TPITCH 136   // fp16 pitch of transpose buffer (16B-aligned rows)

// ===========================================================================
// GEMM1 (fp16): WhT[b][o][j] = (h16 @ W)^T.  (proven R13)
// ===========================================================================
__global__ __launch_bounds__(256, 2)
void gemm1_fp16(const __half* __restrict__ A, const __half* __restrict__ B,
                __half* __restrict__ WhT)
{
    extern __shared__ float smf[];
    const uint32_t sbase = smem_u32(smf);

    const int tid = threadIdx.x;
    const int wid = tid >> 5;
    const int lane = tid & 31;
    const int wm = wid & 3;
    const int wn = wid >> 2;
    const int qid = lane >> 2;
    const int qtr = lane & 3;

    const int jj = lane >> 3, rr = lane & 7;
    const uint32_t a_lane = (uint32_t)(((wm * 32 + (jj & 1) * 8 + rr) * PADU
                                        + (jj >> 1) * 4) * 4);
    const uint32_t b_lane = (uint32_t)(((wn * 64 + (jj >> 1) * 8 + rr) * PADU
                                        + (jj & 1) * 4) * 4);

    const __half* Az = A + (size_t)(blockIdx.y * BM) * FF;
    const __half* Bz = B + (size_t)(blockIdx.x * BN) * FF;

    float acc[2][8][4];
#pragma unroll
    for (int i = 0; i < 2; i++)
#pragma unroll
        for (int j = 0; j < 8; j++)
#pragma unroll
            for (int c = 0; c < 4; c++) acc[i][j][c] = 0.f;

    auto issue_tile = [&](int t, int stage) {
        const __half* Aa = Az + t * BK2;
        const __half* Ba = Bz + t * BK2;
        const uint32_t abase = sbase + stage * (STAGE2_U * 4);
        const uint32_t bbase = abase + A2_TILE_U * 4;
#pragma unroll
        for (int l = 0; l < 4; l++) {
            int idx = tid + l * 256;
            int r = idx >> 3, c = idx & 7;
            cp16(abase + (uint32_t)(r * PADU * 4 + c * 16),
                 Aa + (size_t)r * FF + c * 8);
        }
#pragma unroll
        for (int l = 0; l < 4; l++) {
            int idx = tid + l * 256;
            int r = idx >> 3, c = idx & 7;
            cp16(bbase + (uint32_t)(r * PADU * 4 + c * 16),
                 Ba + (size_t)r * FF + c * 8);
        }
        asm volatile("cp.async.commit_group;" ::: "memory");
    };

    const int T = FF / BK2;   // 4
    issue_tile(0, 0);
    issue_tile(1, 1);

    for (int t = 0; t < T; t++) {
        if (t < T - 1) {
            asm volatile("cp.async.wait_group 1;" ::: "memory");
        } else {
            asm volatile("cp.async.wait_group 0;" ::: "memory");
        }
        __syncthreads();
        if (t + 2 < T) issue_tile(t + 2, (t + 2) % 3);

        const uint32_t stage_b = sbase + (uint32_t)((t % 3) * (STAGE2_U * 4));
        const uint32_t As_b = stage_b;
        const uint32_t Bs_b = stage_b + A2_TILE_U * 4;

#pragma unroll
        for (int kk = 0; kk < 4; kk++) {
            const uint32_t kboff = (uint32_t)(kk * 8 * 4);
            uint32_t af[2][4];
            ldm_x4(af[0][0], af[0][1], af[0][2], af[0][3], As_b + a_lane + kboff);
            ldm_x4(af[1][0], af[1][1], af[1][2], af[1][3],
                   As_b + a_lane + (uint32_t)(16 * PADU * 4) + kboff);
            uint32_t bf[8][2];
#pragma unroll
            for (int nfp = 0; nfp < 4; nfp++) {
                uint32_t d0, d1, d2, d3;
                ldm_x4(d0, d1, d2, d3,
                       Bs_b + b_lane + (uint32_t)(nfp * 16 * PADU * 4) + kboff);
                bf[nfp * 2][0] = d0;     bf[nfp * 2][1] = d1;
                bf[nfp * 2 + 1][0] = d2; bf[nfp * 2 + 1][1] = d3;
            }
#pragma unroll
            for (int mf = 0; mf < 2; mf++)
#pragma unroll
                for (int nf = 0; nf < 8; nf++)
                    mma_f16(acc[mf][nf], af[mf], bf[nf]);
        }
    }

    // ---- Transpose via SMEM, then coalesced fp16 stores ----
    __syncthreads();   // smem stages no longer needed; reuse as transpose buf
    __half* S = (__half*)smf;    // [128 o][TPITCH j]
    const int ob = wn * 64;
#pragma unroll
    for (int mf = 0; mf < 2; mf++) {
#pragma unroll
        for (int half = 0; half < 2; half++) {
            int j_l = wm * 32 + mf * 16 + qid + half * 8;
#pragma unroll
            for (int nf = 0; nf < 8; nf++) {
                int o_l = ob + nf * 8 + qtr * 2;
                S[o_l * TPITCH + j_l]       = __float2half_rn(acc[mf][nf][half * 2]);
                S[(o_l + 1) * TPITCH + j_l] = __float2half_rn(acc[mf][nf][half * 2 + 1]);
            }
        }
    }
    __syncthreads();

    const int r0 = blockIdx.y * BM;
    const int b = r0 >> 10, j0 = r0 & 1023;
    __half* Wb = WhT + (size_t)b * FF * NN + j0;
#pragma unroll
    for (int it = 0; it < 8; it++) {
        int idx = tid + it * 256;          // 0..2047
        int o_l = idx >> 4, jc = idx & 15; // 128 rows x 16 chunks of 16B
        uint4 v = *(uint4*)&S[o_l * TPITCH + jc * 8];
        int o_g = blockIdx.x * BN + o_l;
        *(uint4*)&Wb[(size_t)o_g * NN + jc * 8] = v;
    }
}

// ===========================================================================
// GEMM2 (fp16): out[z] = elu( invden * ( P[z] @ WhT[z]^T ) )  (proven R12/R13)
// ===========================================================================
__global__ __launch_bounds__(256, 2)
void gemm2_fp16(const __half* __restrict__ P,
                const __half* __restrict__ WhT,
                float* __restrict__ out, const float* __restrict__ invden)
{
    extern __shared__ float smf[];
    const uint32_t sbase = smem_u32(smf);
    __shared__ float sInv[BM];

    const int tid = threadIdx.x;
    const int wid = tid >> 5;
    const int lane = tid & 31;
    const int wm = wid & 3;
    const int wn = wid >> 2;
    const int qid = lane >> 2;
    const int qtr = lane & 3;

    const int jj = lane >> 3, rr = lane & 7;
    const uint32_t a_lane = (uint32_t)(((wm * 32 + (jj & 1) * 8 + rr) * PADU
                                        + (jj >> 1) * 4) * 4);
    const uint32_t b_lane = (uint32_t)(((wn * 64 + (jj >> 1) * 8 + rr) * PADU
                                        + (jj & 1) * 4) * 4);

    const __half* Az = P + (size_t)blockIdx.z * NN * NN + (size_t)(blockIdx.y * BM) * NN;
    const __half* Bz = WhT + (size_t)blockIdx.z * FF * NN + (size_t)(blockIdx.x * BN) * NN;
    float* Cz = out + (size_t)blockIdx.z * NN * FF;

    if (tid < BM)
        sInv[tid] = invden[blockIdx.z * NN + blockIdx.y * BM + tid];

    float acc[2][8][4];
#pragma unroll
    for (int i = 0; i < 2; i++)
#pragma unroll
        for (int j = 0; j < 8; j++)
#pragma unroll
            for (int c = 0; c < 4; c++) acc[i][j][c] = 0.f;

    auto issue_tile = [&](int t, int stage) {
        const __half* Aa = Az + t * BK2;
        const __half* Ba = Bz + t * BK2;
        const uint32_t abase = sbase + stage * (STAGE2_U * 4);
        const uint32_t bbase = abase + A2_TILE_U * 4;
#pragma unroll
        for (int l = 0; l < 4; l++) {
            int idx = tid + l * 256;
            int r = idx >> 3, c = idx & 7;
            cp16(abase + (uint32_t)(r * PADU * 4 + c * 16),
                 Aa + (size_t)r * NN + c * 8);
        }
#pragma unroll
        for (int l = 0; l < 4; l++) {
            int idx = tid + l * 256;
            int r = idx >> 3, c = idx & 7;
            cp16(bbase + (uint32_t)(r * PADU * 4 + c * 16),
                 Ba + (size_t)r * NN + c * 8);
        }
        asm volatile("cp.async.commit_group;" ::: "memory");
    };

    const int T = NN / BK2;   // 16
    issue_tile(0, 0);
    issue_tile(1, 1);

    for (int t = 0; t < T; t++) {
        if (t < T - 1) {
            asm volatile("cp.async.wait_group 1;" ::: "memory");
        } else {
            asm volatile("cp.async.wait_group 0;" ::: "memory");
        }
        __syncthreads();
        if (t + 2 < T) issue_tile(t + 2, (t + 2) % 3);

        const uint32_t stage_b = sbase + (uint32_t)((t % 3) * (STAGE2_U * 4));
        const uint32_t As_b = stage_b;
        const uint32_t Bs_b = stage_b + A2_TILE_U * 4;

#pragma unroll
        for (int kk = 0; kk < 4; kk++) {
            const uint32_t kboff = (uint32_t)(kk * 8 * 4);
            uint32_t af[2][4];
            ldm_x4(af[0][0], af[0][1], af[0][2], af[0][3], As_b + a_lane + kboff);
            ldm_x4(af[1][0], af[1][1], af[1][2], af[1][3],
                   As_b + a_lane + (uint32_t)(16 * PADU * 4) + kboff);
            uint32_t bf[8][2];
#pragma unroll
            for (int nfp = 0; nfp < 4; nfp++) {
                uint32_t d0, d1, d2, d3;
                ldm_x4(d0, d1, d2, d3,
                       Bs_b + b_lane + (uint32_t)(nfp * 16 * PADU * 4) + kboff);
                bf[nfp * 2][0] = d0;     bf[nfp * 2][1] = d1;
                bf[nfp * 2 + 1][0] = d2; bf[nfp * 2 + 1][1] = d3;
            }
#pragma unroll
            for (int mf = 0; mf < 2; mf++)
#pragma unroll
                for (int nf = 0; nf < 8; nf++)
                    mma_f16(acc[mf][nf], af[mf], bf[nf]);
        }
    }

    // Epilogue: scale by invden, ELU, store fp32.
    const int col_base = blockIdx.x * BN + wn * 64;
#pragma unroll
    for (int mf = 0; mf < 2; mf++) {
#pragma unroll
        for (int half = 0; half < 2; half++) {
            int rloc = wm * 32 + mf * 16 + qid + half * 8;
            int r = blockIdx.y * BM + rloc;
            float* crow = Cz + (size_t)r * FF;
            float scale = sInv[rloc];
#pragma unroll
            for (int nf = 0; nf < 8; nf++) {
                float x0 = acc[mf][nf][half * 2] * scale;
                float x1 = acc[mf][nf][half * 2 + 1] * scale;
                float2 v;
                v.x = x0 > 0.f ? x0 : expm1f(x0);
                v.y = x1 > 0.f ? x1 : expm1f(x1);
                *(float2*)(crow + col_base + nf * 8 + qtr * 2) = v;
            }
        }
    }
}

// ---------------------------------------------------------------------------
// conv_h: h (fp32) -> h16 (fp16). 8 elems/thread, 16B stores.
// ---------------------------------------------------------------------------
__global__ __launch_bounds__(256)
void conv_h(const float* __restrict__ h, __half* __restrict__ h16)
{
    size_t base = ((size_t)blockIdx.x * 256 + threadIdx.x) * 8;
    float4 a = *(const float4*)(h + base);
    float4 b = *(const float4*)(h + base + 4);
    __half2 h0 = __floats2half2_rn(a.x, a.y);
    __half2 h1 = __floats2half2_rn(a.z, a.w);
    __half2 h2 = __floats2half2_rn(b.x, b.y);
    __half2 h3 = __floats2half2_rn(b.z, b.w);
    uint4 st;
    st.x = *(uint32_t*)&h0; st.y = *(uint32_t*)&h1;
    st.z = *(uint32_t*)&h2; st.w = *(uint32_t*)&h3;
    *(uint4*)(h16 + base) = st;
}

// ---------------------------------------------------------------------------
// conv_wt: Wt16[o][f] = (half)W[f][o]. 32x32 smem tiles.
// ---------------------------------------------------------------------------
__global__ void conv_wt(const float* __restrict__ W, __half* __restrict__ Wt)
{
    __shared__ float t[32][33];
    int x = blockIdx.x * 32 + threadIdx.x;
#pragma unroll
    for (int i = 0; i < 4; i++) {
        int y = blockIdx.y * 32 + threadIdx.y + i * 8;
        t[threadIdx.y + i * 8][threadIdx.x] = W[y * FF + x];
    }
    __syncthreads();
#pragma unroll
    for (int i = 0; i < 4; i++) {
        int o = blockIdx.x * 32 + threadIdx.y + i * 8;
        int f = blockIdx.y * 32 + threadIdx.x;
        Wt[o * FF + f] = __float2half_rn(t[threadIdx.x][threadIdx.y + i * 8]);
    }
}

// ---------------------------------------------------------------------------
// u1 = W @ a1, u2 = W @ a2  (fp32)
// ---------------------------------------------------------------------------
__global__ __launch_bounds__(256)
void ukern(const float* __restrict__ W, const float* __restrict__ a,
           float* __restrict__ u)
{
    int f = blockIdx.x;
    int o = threadIdx.x;
    float w = W[f * FF + o];
    float s1 = w * a[o];
    float s2 = w * a[FF + o];
#pragma unroll
    for (int off = 16; off > 0; off >>= 1) {
        s1 += __shfl_down_sync(0xffffffffu, s1, off);
        s2 += __shfl_down_sync(0xffffffffu, s2, off);
    }
    __shared__ float sh1[8], sh2[8];
    int warp = o >> 5, lane = o & 31;
    if (lane == 0) { sh1[warp] = s1; sh2[warp] = s2; }
    __syncthreads();
    if (o == 0) {
        float t1 = 0.f, t2 = 0.f;
#pragma unroll
        for (int w2 = 0; w2 < 8; w2++) { t1 += sh1[w2]; t2 += sh2[w2]; }
        u[f] = t1;
        u[FF + f] = t2;
    }
}

// ---------------------------------------------------------------------------
// fkern3: warp-per-row. f1[r] = h_row . u1, f2[r] = h_row . u2 (fp32 exact)
// ---------------------------------------------------------------------------
__global__ __launch_bounds__(256)
void fkern3(const float* __restrict__ h, const float* __restrict__ u,
            float* __restrict__ f1, float* __restrict__ f2)
{
    const int warp = threadIdx.x >> 5, lane = threadIdx.x & 31;
    const int row = blockIdx.x * 8 + warp;

    const float4* hp = (const float4*)(h + (size_t)row * FF) + lane * 2;
    float4 h0 = hp[0], h1 = hp[1];
    const float4* u1p = (const float4*)u + lane * 2;
    const float4* u2p = (const float4*)(u + FF) + lane * 2;
    float4 u10 = u1p[0], u11 = u1p[1];
    float4 u20 = u2p[0], u21 = u2p[1];

    float s1 = h0.x * u10.x + h0.y * u10.y + h0.z * u10.z + h0.w * u10.w
             + h1.x * u11.x + h1.y * u11.y + h1.z * u11.z + h1.w * u11.w;
    float s2 = h0.x * u20.x + h0.y * u20.y + h0.z * u20.z + h0.w * u20.w
             + h1.x * u21.x + h1.y * u21.y + h1.z * u21.z + h1.w * u21.w;
#pragma unroll
    for (int o = 16; o > 0; o >>= 1) {
        s1 += __shfl_xor_sync(0xffffffffu, s1, o);
        s2 += __shfl_xor_sync(0xffffffffu, s2, o);
    }
    if (lane == 0) { f1[row] = s1; f2[row] = s2; }
}

// ---------------------------------------------------------------------------
// Per-batch max of f2 (fp16-safe shift). One block per batch.
// ---------------------------------------------------------------------------
__global__ __launch_bounds__(256)
void maxf2kern(const float* __restrict__ f2, float* __restrict__ maxf2)
{
    const int b = blockIdx.x;
    const int t = threadIdx.x;
    float4 v = ((const float4*)(f2 + ((size_t)b << 10)))[t];
    float m = fmaxf(fmaxf(v.x, v.y), fmaxf(v.z, v.w));
#pragma unroll
    for (int o = 16; o > 0; o >>= 1)
        m = fmaxf(m, __shfl_xor_sync(0xffffffffu, m, o));
    __shared__ float red[8];
    int warp = t >> 5, lane = t & 31;
    if (lane == 0) red[warp] = m;
    __syncthreads();
    if (t == 0) {
        float mm = red[0];
#pragma unroll
        for (int w2 = 1; w2 < 8; w2++) mm = fmaxf(mm, red[w2]);
        maxf2[b] = mm;
    }
}

// ---------------------------------------------------------------------------
// Single-pass masked exp -> shifted fp16 P + invden. (proven R11-R13)
// ---------------------------------------------------------------------------
__global__ __launch_bounds__(256)
void attn_p(const int* __restrict__ adj, __half* __restrict__ P,
            const float* __restrict__ f1, const float* __restrict__ f2,
            const float* __restrict__ maxf2, float* __restrict__ invden)
{
    const int row0 = blockIdx.x * 2;
    const int rh = threadIdx.x >> 7;          // 0/1: which row
    const int t = threadIdx.x & 127;
    const int row = row0 + rh;
    const int b = row >> 10;
    const float f1v = __ldg(f1 + row);
    const float fm = f1v + __ldg(maxf2 + b);
    const float M = fm >= 0.f ? fm : ALPHA * fm;   // row upper bound

    const int4* ap = (const int4*)(adj + (size_t)row * NN) + t * 2;
    const float4* fp = (const float4*)(f2 + ((size_t)b << 10)) + t * 2;
    int4 av0 = ap[0], av1 = ap[1];
    float4 f20 = fp[0], f21 = fp[1];

    float p[8];
    {
        float s;
        s = f1v + f20.x; s = s >= 0.f ? s : ALPHA * s; p[0] = (av0.x > 0) ? __expf(s - M) : 0.f;
        s = f1v + f20.y; s = s >= 0.f ? s : ALPHA * s; p[1] = (av0.y > 0) ? __expf(s - M) : 0.f;
        s = f1v + f20.z; s = s >= 0.f ? s : ALPHA * s; p[2] = (av0.z > 0) ? __expf(s - M) : 0.f;
        s = f1v + f20.w; s = s >= 0.f ? s : ALPHA * s; p[3] = (av0.w > 0) ? __expf(s - M) : 0.f;
        s = f1v + f21.x; s = s >= 0.f ? s : ALPHA * s; p[4] = (av1.x > 0) ? __expf(s - M) : 0.f;
        s = f1v + f21.y; s = s >= 0.f ? s : ALPHA * s; p[5] = (av1.y > 0) ? __expf(s - M) : 0.f;
        s = f1v + f21.z; s = s >= 0.f ? s : ALPHA * s; p[6] = (av1.z > 0) ? __expf(s - M) : 0.f;
        s = f1v + f21.w; s = s >= 0.f ? s : ALPHA * s; p[7] = (av1.w > 0) ? __expf(s - M) : 0.f;
    }

    __half2 h0 = __floats2half2_rn(p[0], p[1]);
    __half2 h1 = __floats2half2_rn(p[2], p[3]);
    __half2 h2 = __floats2half2_rn(p[4], p[5]);
    __half2 h3 = __floats2half2_rn(p[6], p[7]);
    uint4 st;
    st.x = *(uint32_t*)&h0; st.y = *(uint32_t*)&h1;
    st.z = *(uint32_t*)&h2; st.w = *(uint32_t*)&h3;
    ((uint4*)(P + (size_t)row * NN))[t] = st;

    float sum = ((p[0] + p[1]) + (p[2] + p[3])) + ((p[4] + p[5]) + (p[6] + p[7]));
#pragma unroll
    for (int o = 16; o > 0; o >>= 1)
        sum += __shfl_xor_sync(0xffffffffu, sum, o);

    __shared__ float red[8];
    int warp = threadIdx.x >> 5, lane = threadIdx.x & 31;
    if (lane == 0) red[warp] = sum;
    __syncthreads();
    if (threadIdx.x < 2) {
        int base = threadIdx.x * 4;
        float tot = (red[base] + red[base + 1]) + (red[base + 2] + red[base + 3]);
        invden[row0 + threadIdx.x] = 1.0f / tot;
    }
}

// ---------------------------------------------------------------------------
// Launch
// ---------------------------------------------------------------------------
extern "C" void kernel_launch(void* const* d_in, const int* in_sizes, int n_in,
                              void* d_out, int out_size)
{
    const float* h   = (const float*)d_in[0];   // [16,1024,256]
    const int*   adj = (const int*)d_in[1];     // [16,1024,1024]
    const float* W   = (const float*)d_in[2];   // [256,256]
    const float* a   = (const float*)d_in[3];   // [512,1]
    float* out = (float*)d_out;                 // [16,1024,256]

    __half *h16, *Wt16, *WhT, *P;
    float *u, *f1, *f2, *maxf2, *invden;
    cudaGetSymbolAddress((void**)&h16,    g_h16);
    cudaGetSymbolAddress((void**)&Wt16,   g_Wt16);
    cudaGetSymbolAddress((void**)&WhT,    g_WhT);
    cudaGetSymbolAddress((void**)&u,      g_u);
    cudaGetSymbolAddress((void**)&f1,     g_f1);
    cudaGetSymbolAddress((void**)&f2,     g_f2);
    cudaGetSymbolAddress((void**)&maxf2,  g_maxf2);
    cudaGetSymbolAddress((void**)&P,      g_P);
    cudaGetSymbolAddress((void**)&invden, g_invden);

    cudaFuncSetAttribute((const void*)gemm1_fp16,
                         cudaFuncAttributeMaxDynamicSharedMemorySize, G2_SMEM);
    cudaFuncSetAttribute((const void*)gemm2_fp16,
                         cudaFuncAttributeMaxDynamicSharedMemorySize, G2_SMEM);

    // 1) conversions: h -> fp16, W -> W^T fp16
    conv_h<<<(BB * NN * FF) / 2048, 256>>>(h, h16);
    conv_wt<<<dim3(8, 8), dim3(32, 8)>>>(W, Wt16);

    // 2) u1,u2 = W@a1, W@a2 (fp32)
    ukern<<<FF, 256>>>(W, a, u);

    // 3) f1,f2 = h@u1, h@u2 (fp32, warp-per-row — softmax logits exact)
    fkern3<<<(BB * NN) / 8, 256>>>(h, u, f1, f2);

    // 4) per-batch max of f2 (fp16-safe shift)
    maxf2kern<<<BB, 256>>>(f2, maxf2);

    // 5) WhT = (h16 @ W)^T per batch (fp16 mma, ldmatrix, SMEM-transposed)
    gemm1_fp16<<<dim3(FF / BN, (BB * NN) / BM, 1), 256, G2_SMEM>>>(h16, Wt16, WhT);

    // 6) single-pass masked shifted exp -> fp16 P + invden
    attn_p<<<(BB * NN) / 2, 256>>>(adj, P, f1, f2, maxf2, invden);

    // 7) out = elu( invden * (P @ Wh) )  (fp16 mma, ldmatrix, 3-stage pipeline)
    gemm2_fp16<<<dim3(FF / BN, NN / BM, BB), 256, G2_SMEM>>>(P, WhT, out, invden);
}

// round 17
// speedup vs baseline: 1.0276x; 1.0276x over previous
#include <cuda_runtime.h>
#include <cuda_fp16.h>
#include <math.h>
#include <stdint.h>

// Problem constants
#define BB 16
#define NN 1024
#define FF 256
#define ALPHA 0.2f

// Scratch (device globals — no allocations allowed)
__device__ __half g_h16[(size_t)BB * NN * FF];      // 8 MB  h in fp16
__device__ __half g_Wt16[FF * FF];                  // W^T fp16 [o][f]
__device__ __half g_WhT[(size_t)BB * FF * NN];      // 8 MB  [b][o][j] fp16
__device__ float g_u[2 * FF];                       // u1 = W@a1, u2 = W@a2
__device__ float g_f1[BB * NN];
__device__ float g_f2[BB * NN];
__device__ float g_maxf2[BB];
__device__ __half g_P[(size_t)BB * NN * NN];        // 32 MB shifted exp, fp16
__device__ float g_invden[BB * NN];                 // 1 / row sum (of shifted exps)

// ---------------------------------------------------------------------------
// Helpers
// ---------------------------------------------------------------------------
__device__ __forceinline__ void cp16(uint32_t saddr, const void* gptr) {
    asm volatile("cp.async.cg.shared.global [%0], [%1], 16;"
                 :: "r"(saddr), "l"(gptr) : "memory");
}

__device__ __forceinline__ uint32_t smem_u32(const void* p) {
    uint32_t a;
    asm("{ .reg .u64 t; cvta.to.shared.u64 t, %1; cvt.u32.u64 %0, t; }"
        : "=r"(a) : "l"(p));
    return a;
}

__device__ __forceinline__ void mma_f16(float* c, const uint32_t* a, const uint32_t* b) {
    asm volatile(
        "mma.sync.aligned.m16n8k16.row.col.f32.f16.f16.f32 "
        "{%0,%1,%2,%3}, {%4,%5,%6,%7}, {%8,%9}, {%0,%1,%2,%3};"
        : "+f"(c[0]), "+f"(c[1]), "+f"(c[2]), "+f"(c[3])
        : "r"(a[0]), "r"(a[1]), "r"(a[2]), "r"(a[3]), "r"(b[0]), "r"(b[1]));
}

__device__ __forceinline__ void ldm_x4(uint32_t& d0, uint32_t& d1,
                                       uint32_t& d2, uint32_t& d3, uint32_t a) {
    asm volatile("ldmatrix.sync.aligned.m8n8.x4.shared.b16 {%0,%1,%2,%3}, [%4];"
                 : "=r"(d0), "=r"(d1), "=r"(d2), "=r"(d3) : "r"(a));
}

// Shared tile geometry (both fp16 GEMMs)
#define BM 128
#define BN 128
#define BK2 64
#define PADU 36                       // u32 row pitch (32 data + 4 pad)
#define A2_TILE_U (128 * PADU)
#define B2_TILE_U (128 * PADU)
#define STAGE2_U (A2_TILE_U + B2_TILE_U)    // 9216 u32 = 36864 B
#define G2_SMEM (3 * STAGE2_U * 4)          // 110592 B
#define TPITCH 136   // fp16 pitch of transpose buffer (16B-aligned rows)

// ===========================================================================
// GEMM1 (fp16): WhT[b][o][j] = (h16 @ W)^T.  (proven R13/R16)
// ===========================================================================
__global__ __launch_bounds__(256, 2)
void gemm1_fp16(const __half* __restrict__ A, const __half* __restrict__ B,
                __half* __restrict__ WhT)
{
    extern __shared__ float smf[];
    const uint32_t sbase = smem_u32(smf);

    const int tid = threadIdx.x;
    const int wid = tid >> 5;
    const int lane = tid & 31;
    const int wm = wid & 3;
    const int wn = wid >> 2;
    const int qid = lane >> 2;
    const int qtr = lane & 3;

    const int jj = lane >> 3, rr = lane & 7;
    const uint32_t a_lane = (uint32_t)(((wm * 32 + (jj & 1) * 8 + rr) * PADU
                                        + (jj >> 1) * 4) * 4);
    const uint32_t b_lane = (uint32_t)(((wn * 64 + (jj >> 1) * 8 + rr) * PADU
                                        + (jj & 1) * 4) * 4);

    const __half* Az = A + (size_t)(blockIdx.y * BM) * FF;
    const __half* Bz = B + (size_t)(blockIdx.x * BN) * FF;

    float acc[2][8][4];
#pragma unroll
    for (int i = 0; i < 2; i++)
#pragma unroll
        for (int j = 0; j < 8; j++)
#pragma unroll
            for (int c = 0; c < 4; c++) acc[i][j][c] = 0.f;

    auto issue_tile = [&](int t, int stage) {
        const __half* Aa = Az + t * BK2;
        const __half* Ba = Bz + t * BK2;
        const uint32_t abase = sbase + stage * (STAGE2_U * 4);
        const uint32_t bbase = abase + A2_TILE_U * 4;
#pragma unroll
        for (int l = 0; l < 4; l++) {
            int idx = tid + l * 256;
            int r = idx >> 3, c = idx & 7;
            cp16(abase + (uint32_t)(r * PADU * 4 + c * 16),
                 Aa + (size_t)r * FF + c * 8);
        }
#pragma unroll
        for (int l = 0; l < 4; l++) {
            int idx = tid + l * 256;
            int r = idx >> 3, c = idx & 7;
            cp16(bbase + (uint32_t)(r * PADU * 4 + c * 16),
                 Ba + (size_t)r * FF + c * 8);
        }
        asm volatile("cp.async.commit_group;" ::: "memory");
    };

    const int T = FF / BK2;   // 4
    issue_tile(0, 0);
    issue_tile(1, 1);

    for (int t = 0; t < T; t++) {
        if (t < T - 1) {
            asm volatile("cp.async.wait_group 1;" ::: "memory");
        } else {
            asm volatile("cp.async.wait_group 0;" ::: "memory");
        }
        __syncthreads();
        if (t + 2 < T) issue_tile(t + 2, (t + 2) % 3);

        const uint32_t stage_b = sbase + (uint32_t)((t % 3) * (STAGE2_U * 4));
        const uint32_t As_b = stage_b;
        const uint32_t Bs_b = stage_b + A2_TILE_U * 4;

#pragma unroll
        for (int kk = 0; kk < 4; kk++) {
            const uint32_t kboff = (uint32_t)(kk * 8 * 4);
            uint32_t af[2][4];
            ldm_x4(af[0][0], af[0][1], af[0][2], af[0][3], As_b + a_lane + kboff);
            ldm_x4(af[1][0], af[1][1], af[1][2], af[1][3],
                   As_b + a_lane + (uint32_t)(16 * PADU * 4) + kboff);
            uint32_t bf[8][2];
#pragma unroll
            for (int nfp = 0; nfp < 4; nfp++) {
                uint32_t d0, d1, d2, d3;
                ldm_x4(d0, d1, d2, d3,
                       Bs_b + b_lane + (uint32_t)(nfp * 16 * PADU * 4) + kboff);
                bf[nfp * 2][0] = d0;     bf[nfp * 2][1] = d1;
                bf[nfp * 2 + 1][0] = d2; bf[nfp * 2 + 1][1] = d3;
            }
#pragma unroll
            for (int mf = 0; mf < 2; mf++)
#pragma unroll
                for (int nf = 0; nf < 8; nf++)
                    mma_f16(acc[mf][nf], af[mf], bf[nf]);
        }
    }

    // ---- Transpose via SMEM, then coalesced fp16 stores ----
    __syncthreads();   // smem stages no longer needed; reuse as transpose buf
    __half* S = (__half*)smf;    // [128 o][TPITCH j]
    const int ob = wn * 64;
#pragma unroll
    for (int mf = 0; mf < 2; mf++) {
#pragma unroll
        for (int half = 0; half < 2; half++) {
            int j_l = wm * 32 + mf * 16 + qid + half * 8;
#pragma unroll
            for (int nf = 0; nf < 8; nf++) {
                int o_l = ob + nf * 8 + qtr * 2;
                S[o_l * TPITCH + j_l]       = __float2half_rn(acc[mf][nf][half * 2]);
                S[(o_l + 1) * TPITCH + j_l] = __float2half_rn(acc[mf][nf][half * 2 + 1]);
            }
        }
    }
    __syncthreads();

    const int r0 = blockIdx.y * BM;
    const int b = r0 >> 10, j0 = r0 & 1023;
    __half* Wb = WhT + (size_t)b * FF * NN + j0;
#pragma unroll
    for (int it = 0; it < 8; it++) {
        int idx = tid + it * 256;          // 0..2047
        int o_l = idx >> 4, jc = idx & 15; // 128 rows x 16 chunks of 16B
        uint4 v = *(uint4*)&S[o_l * TPITCH + jc * 8];
        int o_g = blockIdx.x * BN + o_l;
        *(uint4*)&Wb[(size_t)o_g * NN + jc * 8] = v;
    }
}

// ===========================================================================
// GEMM2 (fp16): out[z] = elu( invden * ( P[z] @ WhT[z]^T ) )  (proven)
// ===========================================================================
__global__ __launch_bounds__(256, 2)
void gemm2_fp16(const __half* __restrict__ P,
                const __half* __restrict__ WhT,
                float* __restrict__ out, const float* __restrict__ invden)
{
    extern __shared__ float smf[];
    const uint32_t sbase = smem_u32(smf);
    __shared__ float sInv[BM];

    const int tid = threadIdx.x;
    const int wid = tid >> 5;
    const int lane = tid & 31;
    const int wm = wid & 3;
    const int wn = wid >> 2;
    const int qid = lane >> 2;
    const int qtr = lane & 3;

    const int jj = lane >> 3, rr = lane & 7;
    const uint32_t a_lane = (uint32_t)(((wm * 32 + (jj & 1) * 8 + rr) * PADU
                                        + (jj >> 1) * 4) * 4);
    const uint32_t b_lane = (uint32_t)(((wn * 64 + (jj >> 1) * 8 + rr) * PADU
                                        + (jj & 1) * 4) * 4);

    const __half* Az = P + (size_t)blockIdx.z * NN * NN + (size_t)(blockIdx.y * BM) * NN;
    const __half* Bz = WhT + (size_t)blockIdx.z * FF * NN + (size_t)(blockIdx.x * BN) * NN;
    float* Cz = out + (size_t)blockIdx.z * NN * FF;

    if (tid < BM)
        sInv[tid] = invden[blockIdx.z * NN + blockIdx.y * BM + tid];

    float acc[2][8][4];
#pragma unroll
    for (int i = 0; i < 2; i++)
#pragma unroll
        for (int j = 0; j < 8; j++)
#pragma unroll
            for (int c = 0; c < 4; c++) acc[i][j][c] = 0.f;

    auto issue_tile = [&](int t, int stage) {
        const __half* Aa = Az + t * BK2;
        const __half* Ba = Bz + t * BK2;
        const uint32_t abase = sbase + stage * (STAGE2_U * 4);
        const uint32_t bbase = abase + A2_TILE_U * 4;
#pragma unroll
        for (int l = 0; l < 4; l++) {
            int idx = tid + l * 256;
            int r = idx >> 3, c = idx & 7;
            cp16(abase + (uint32_t)(r * PADU * 4 + c * 16),
                 Aa + (size_t)r * NN + c * 8);
        }
#pragma unroll
        for (int l = 0; l < 4; l++) {
            int idx = tid + l * 256;
            int r = idx >> 3, c = idx & 7;
            cp16(bbase + (uint32_t)(r * PADU * 4 + c * 16),
                 Ba + (size_t)r * NN + c * 8);
        }
        asm volatile("cp.async.commit_group;" ::: "memory");
    };

    const int T = NN / BK2;   // 16
    issue_tile(0, 0);
    issue_tile(1, 1);

    for (int t = 0; t < T; t++) {
        if (t < T - 1) {
            asm volatile("cp.async.wait_group 1;" ::: "memory");
        } else {
            asm volatile("cp.async.wait_group 0;" ::: "memory");
        }
        __syncthreads();
        if (t + 2 < T) issue_tile(t + 2, (t + 2) % 3);

        const uint32_t stage_b = sbase + (uint32_t)((t % 3) * (STAGE2_U * 4));
        const uint32_t As_b = stage_b;
        const uint32_t Bs_b = stage_b + A2_TILE_U * 4;

#pragma unroll
        for (int kk = 0; kk < 4; kk++) {
            const uint32_t kboff = (uint32_t)(kk * 8 * 4);
            uint32_t af[2][4];
            ldm_x4(af[0][0], af[0][1], af[0][2], af[0][3], As_b + a_lane + kboff);
            ldm_x4(af[1][0], af[1][1], af[1][2], af[1][3],
                   As_b + a_lane + (uint32_t)(16 * PADU * 4) + kboff);
            uint32_t bf[8][2];
#pragma unroll
            for (int nfp = 0; nfp < 4; nfp++) {
                uint32_t d0, d1, d2, d3;
                ldm_x4(d0, d1, d2, d3,
                       Bs_b + b_lane + (uint32_t)(nfp * 16 * PADU * 4) + kboff);
                bf[nfp * 2][0] = d0;     bf[nfp * 2][1] = d1;
                bf[nfp * 2 + 1][0] = d2; bf[nfp * 2 + 1][1] = d3;
            }
#pragma unroll
            for (int mf = 0; mf < 2; mf++)
#pragma unroll
                for (int nf = 0; nf < 8; nf++)
                    mma_f16(acc[mf][nf], af[mf], bf[nf]);
        }
    }

    // Epilogue: scale by invden, ELU, store fp32.
    const int col_base = blockIdx.x * BN + wn * 64;
#pragma unroll
    for (int mf = 0; mf < 2; mf++) {
#pragma unroll
        for (int half = 0; half < 2; half++) {
            int rloc = wm * 32 + mf * 16 + qid + half * 8;
            int r = blockIdx.y * BM + rloc;
            float* crow = Cz + (size_t)r * FF;
            float scale = sInv[rloc];
#pragma unroll
            for (int nf = 0; nf < 8; nf++) {
                float x0 = acc[mf][nf][half * 2] * scale;
                float x1 = acc[mf][nf][half * 2 + 1] * scale;
                float2 v;
                v.x = x0 > 0.f ? x0 : expm1f(x0);
                v.y = x1 > 0.f ? x1 : expm1f(x1);
                *(float2*)(crow + col_base + nf * 8 + qtr * 2) = v;
            }
        }
    }
}

// ---------------------------------------------------------------------------
// conv_h: h (fp32) -> h16 (fp16). 8 elems/thread, 16B stores.
// ---------------------------------------------------------------------------
__global__ __launch_bounds__(256)
void conv_h(const float* __restrict__ h, __half* __restrict__ h16)
{
    size_t base = ((size_t)blockIdx.x * 256 + threadIdx.x) * 8;
    float4 a = *(const float4*)(h + base);
    float4 b = *(const float4*)(h + base + 4);
    __half2 h0 = __floats2half2_rn(a.x, a.y);
    __half2 h1 = __floats2half2_rn(a.z, a.w);
    __half2 h2 = __floats2half2_rn(b.x, b.y);
    __half2 h3 = __floats2half2_rn(b.z, b.w);
    uint4 st;
    st.x = *(uint32_t*)&h0; st.y = *(uint32_t*)&h1;
    st.z = *(uint32_t*)&h2; st.w = *(uint32_t*)&h3;
    *(uint4*)(h16 + base) = st;
}

// ---------------------------------------------------------------------------
// conv_wt: Wt16[o][f] = (half)W[f][o]. 32x32 smem tiles.
// ---------------------------------------------------------------------------
__global__ void conv_wt(const float* __restrict__ W, __half* __restrict__ Wt)
{
    __shared__ float t[32][33];
    int x = blockIdx.x * 32 + threadIdx.x;
#pragma unroll
    for (int i = 0; i < 4; i++) {
        int y = blockIdx.y * 32 + threadIdx.y + i * 8;
        t[threadIdx.y + i * 8][threadIdx.x] = W[y * FF + x];
    }
    __syncthreads();
#pragma unroll
    for (int i = 0; i < 4; i++) {
        int o = blockIdx.x * 32 + threadIdx.y + i * 8;
        int f = blockIdx.y * 32 + threadIdx.x;
        Wt[o * FF + f] = __float2half_rn(t[threadIdx.x][threadIdx.y + i * 8]);
    }
}

// ---------------------------------------------------------------------------
// u1 = W @ a1, u2 = W @ a2  (fp32)
// ---------------------------------------------------------------------------
__global__ __launch_bounds__(256)
void ukern(const float* __restrict__ W, const float* __restrict__ a,
           float* __restrict__ u)
{
    int f = blockIdx.x;
    int o = threadIdx.x;
    float w = W[f * FF + o];
    float s1 = w * a[o];
    float s2 = w * a[FF + o];
#pragma unroll
    for (int off = 16; off > 0; off >>= 1) {
        s1 += __shfl_down_sync(0xffffffffu, s1, off);
        s2 += __shfl_down_sync(0xffffffffu, s2, off);
    }
    __shared__ float sh1[8], sh2[8];
    int warp = o >> 5, lane = o & 31;
    if (lane == 0) { sh1[warp] = s1; sh2[warp] = s2; }
    __syncthreads();
    if (o == 0) {
        float t1 = 0.f, t2 = 0.f;
#pragma unroll
        for (int w2 = 0; w2 < 8; w2++) { t1 += sh1[w2]; t2 += sh2[w2]; }
        u[f] = t1;
        u[FF + f] = t2;
    }
}

// ---------------------------------------------------------------------------
// fkern4: 4 rows per warp (MLP=8 front-batched loads), same per-row
// arithmetic as fkern3 -> bit-identical f1/f2. grid = 16384/32 = 512 blocks.
// ---------------------------------------------------------------------------
__global__ __launch_bounds__(256)
void fkern4(const float* __restrict__ h, const float* __restrict__ u,
            float* __restrict__ f1, float* __restrict__ f2)
{
    const int warp = threadIdx.x >> 5, lane = threadIdx.x & 31;
    const int row0 = blockIdx.x * 32 + warp * 4;

    // Front-batched loads: 8 independent LDG.128 per thread
    float4 ha[4][2];
#pragma unroll
    for (int r = 0; r < 4; r++) {
        const float4* hp = (const float4*)(h + (size_t)(row0 + r) * FF) + lane * 2;
        ha[r][0] = hp[0];
        ha[r][1] = hp[1];
    }

    const float4* u1p = (const float4*)u + lane * 2;
    const float4* u2p = (const float4*)(u + FF) + lane * 2;
    float4 u10 = u1p[0], u11 = u1p[1];
    float4 u20 = u2p[0], u21 = u2p[1];

#pragma unroll
    for (int r = 0; r < 4; r++) {
        float4 h0 = ha[r][0], h1 = ha[r][1];
        float s1 = h0.x * u10.x + h0.y * u10.y + h0.z * u10.z + h0.w * u10.w
                 + h1.x * u11.x + h1.y * u11.y + h1.z * u11.z + h1.w * u11.w;
        float s2 = h0.x * u20.x + h0.y * u20.y + h0.z * u20.z + h0.w * u20.w
                 + h1.x * u21.x + h1.y * u21.y + h1.z * u21.z + h1.w * u21.w;
#pragma unroll
        for (int o = 16; o > 0; o >>= 1) {
            s1 += __shfl_xor_sync(0xffffffffu, s1, o);
            s2 += __shfl_xor_sync(0xffffffffu, s2, o);
        }
        if (lane == 0) { f1[row0 + r] = s1; f2[row0 + r] = s2; }
    }
}

// ---------------------------------------------------------------------------
// Per-batch max of f2 (fp16-safe shift). One block per batch.
// ---------------------------------------------------------------------------
__global__ __launch_bounds__(256)
void maxf2kern(const float* __restrict__ f2, float* __restrict__ maxf2)
{
    const int b = blockIdx.x;
    const int t = threadIdx.x;
    float4 v = ((const float4*)(f2 + ((size_t)b << 10)))[t];
    float m = fmaxf(fmaxf(v.x, v.y), fmaxf(v.z, v.w));
#pragma unroll
    for (int o = 16; o > 0; o >>= 1)
        m = fmaxf(m, __shfl_xor_sync(0xffffffffu, m, o));
    __shared__ float red[8];
    int warp = t >> 5, lane = t & 31;
    if (lane == 0) red[warp] = m;
    __syncthreads();
    if (t == 0) {
        float mm = red[0];
#pragma unroll
        for (int w2 = 1; w2 < 8; w2++) mm = fmaxf(mm, red[w2]);
        maxf2[b] = mm;
    }
}

// ---------------------------------------------------------------------------
// Single-pass masked exp -> shifted fp16 P + invden. (proven R11-R16)
// ---------------------------------------------------------------------------
__global__ __launch_bounds__(256)
void attn_p(const int* __restrict__ adj, __half* __restrict__ P,
            const float* __restrict__ f1, const float* __restrict__ f2,
            const float* __restrict__ maxf2, float* __restrict__ invden)
{
    const int row0 = blockIdx.x * 2;
    const int rh = threadIdx.x >> 7;          // 0/1: which row
    const int t = threadIdx.x & 127;
    const int row = row0 + rh;
    const int b = row >> 10;
    const float f1v = __ldg(f1 + row);
    const float fm = f1v + __ldg(maxf2 + b);
    const float M = fm >= 0.f ? fm : ALPHA * fm;   // row upper bound

    const int4* ap = (const int4*)(adj + (size_t)row * NN) + t * 2;
    const float4* fp = (const float4*)(f2 + ((size_t)b << 10)) + t * 2;
    int4 av0 = ap[0], av1 = ap[1];
    float4 f20 = fp[0], f21 = fp[1];

    float p[8];
    {
        float s;
        s = f1v + f20.x; s = s >= 0.f ? s : ALPHA * s; p[0] = (av0.x > 0) ? __expf(s - M) : 0.f;
        s = f1v + f20.y; s = s >= 0.f ? s : ALPHA * s; p[1] = (av0.y > 0) ? __expf(s - M) : 0.f;
        s = f1v + f20.z; s = s >= 0.f ? s : ALPHA * s; p[2] = (av0.z > 0) ? __expf(s - M) : 0.f;
        s = f1v + f20.w; s = s >= 0.f ? s : ALPHA * s; p[3] = (av0.w > 0) ? __expf(s - M) : 0.f;
        s = f1v + f21.x; s = s >= 0.f ? s : ALPHA * s; p[4] = (av1.x > 0) ? __expf(s - M) : 0.f;
        s = f1v + f21.y; s = s >= 0.f ? s : ALPHA * s; p[5] = (av1.y > 0) ? __expf(s - M) : 0.f;
        s = f1v + f21.z; s = s >= 0.f ? s : ALPHA * s; p[6] = (av1.z > 0) ? __expf(s - M) : 0.f;
        s = f1v + f21.w; s = s >= 0.f ? s : ALPHA * s; p[7] = (av1.w > 0) ? __expf(s - M) : 0.f;
    }

    __half2 h0 = __floats2half2_rn(p[0], p[1]);
    __half2 h1 = __floats2half2_rn(p[2], p[3]);
    __half2 h2 = __floats2half2_rn(p[4], p[5]);
    __half2 h3 = __floats2half2_rn(p[6], p[7]);
    uint4 st;
    st.x = *(uint32_t*)&h0; st.y = *(uint32_t*)&h1;
    st.z = *(uint32_t*)&h2; st.w = *(uint32_t*)&h3;
    ((uint4*)(P + (size_t)row * NN))[t] = st;

    float sum = ((p[0] + p[1]) + (p[2] + p[3])) + ((p[4] + p[5]) + (p[6] + p[7]));
#pragma unroll
    for (int o = 16; o > 0; o >>= 1)
        sum += __shfl_xor_sync(0xffffffffu, sum, o);

    __shared__ float red[8];
    int warp = threadIdx.x >> 5, lane = threadIdx.x & 31;
    if (lane == 0) red[warp] = sum;
    __syncthreads();
    if (threadIdx.x < 2) {
        int base = threadIdx.x * 4;
        float tot = (red[base] + red[base + 1]) + (red[base + 2] + red[base + 3]);
        invden[row0 + threadIdx.x] = 1.0f / tot;
    }
}

// ---------------------------------------------------------------------------
// Launch
// ---------------------------------------------------------------------------
extern "C" void kernel_launch(void* const* d_in, const int* in_sizes, int n_in,
                              void* d_out, int out_size)
{
    const float* h   = (const float*)d_in[0];   // [16,1024,256]
    const int*   adj = (const int*)d_in[1];     // [16,1024,1024]
    const float* W   = (const float*)d_in[2];   // [256,256]
    const float* a   = (const float*)d_in[3];   // [512,1]
    float* out = (float*)d_out;                 // [16,1024,256]

    __half *h16, *Wt16, *WhT, *P;
    float *u, *f1, *f2, *maxf2, *invden;
    cudaGetSymbolAddress((void**)&h16,    g_h16);
    cudaGetSymbolAddress((void**)&Wt16,   g_Wt16);
    cudaGetSymbolAddress((void**)&WhT,    g_WhT);
    cudaGetSymbolAddress((void**)&u,      g_u);
    cudaGetSymbolAddress((void**)&f1,     g_f1);
    cudaGetSymbolAddress((void**)&f2,     g_f2);
    cudaGetSymbolAddress((void**)&maxf2,  g_maxf2);
    cudaGetSymbolAddress((void**)&P,      g_P);
    cudaGetSymbolAddress((void**)&invden, g_invden);

    cudaFuncSetAttribute((const void*)gemm1_fp16,
                         cudaFuncAttributeMaxDynamicSharedMemorySize, G2_SMEM);
    cudaFuncSetAttribute((const void*)gemm2_fp16,
                         cudaFuncAttributeMaxDynamicSharedMemorySize, G2_SMEM);

    // 1) conversions: h -> fp16, W -> W^T fp16
    conv_h<<<(BB * NN * FF) / 2048, 256>>>(h, h16);
    conv_wt<<<dim3(8, 8), dim3(32, 8)>>>(W, Wt16);

    // 2) u1,u2 = W@a1, W@a2 (fp32)
    ukern<<<FF, 256>>>(W, a, u);

    // 3) f1,f2 = h@u1, h@u2 (fp32, 4 rows/warp — softmax logits exact)
    fkern4<<<(BB * NN) / 32, 256>>>(h, u, f1, f2);

    // 4) per-batch max of f2 (fp16-safe shift)
    maxf2kern<<<BB, 256>>>(f2, maxf2);

    // 5) WhT = (h16 @ W)^T per batch (fp16 mma, ldmatrix, SMEM-transposed)
    gemm1_fp16<<<dim3(FF / BN, (BB * NN) / BM, 1), 256, G2_SMEM>>>(h16, Wt16, WhT);

    // 6) single-pass masked shifted exp -> fp16 P + invden
    attn_p<<<(BB * NN) / 2, 256>>>(adj, P, f1, f2, maxf2, invden);

    // 7) out = elu( invden * (P @ Wh) )  (fp16 mma, ldmatrix, 3-stage pipeline)
    gemm2_fp16<<<dim3(FF / BN, NN / BM, BB), 256, G2_SMEM>>>(P, WhT, out, invden);
}